// round 7
// baseline (speedup 1.0000x reference)
#include <cuda_runtime.h>

// SpectralConv2d via DHT — fused kernel, 2-D register tiling to cut L1 wavefronts.
//
//   A[i][y]   = sum_k x[b,i,row,k] * B[k][y],   B[k][y]=cas(2pi*k*y/256), y<32
//   r[o][y]   = sum_i A[i][y] * w_blk[i,o,x,y]
//   out[o][k] = sum_y r[o][y] * M[y][k]   for the 64 live rows; 0 elsewhere
//   M[y][k]   = ( sum_j cas(2pi*y*j/32) * cas(2pi*j*k/256) ) * 2^-42

#define NB 8
#define S  256

// g_B2[kc2*16+yp] = {B[2kc2][2yp], B[2kc2][2yp+1], B[2kc2+1][2yp], B[2kc2+1][2yp+1]}
__device__ float4 g_B2[128 * 16];
__device__ float  g_M[32 * 256];   // folded trailing transforms

// ---------------------------------------------------------------------------
// K0: build g_B2 and the folded 32x256 matrix M.
// ---------------------------------------------------------------------------
__global__ void k0_tables() {
    __shared__ float c256[256];
    __shared__ float c32[32];
    const float TWO_PI = 6.283185307179586476925286766559f;
    int t = threadIdx.x;
    {
        float s, c;
        sincosf((TWO_PI / 256.0f) * (float)t, &s, &c);
        c256[t] = c + s;
        if (t < 32) {
            float s2, c2;
            sincosf((TWO_PI / 32.0f) * (float)t, &s2, &c2);
            c32[t] = c2 + s2;
        }
    }
    __syncthreads();
    int gid = blockIdx.x * 256 + t;          // 0..8191
    {   // M[y][k]
        int y = gid >> 8, k = gid & 255;
        float acc = 0.0f;
#pragma unroll
        for (int j = 0; j < 32; j++)
            acc += c32[(y * j) & 31] * c256[(j * k) & 255];
        g_M[gid] = acc * 0x1p-42f;
    }
    if (gid < 2048) {                        // g_B2[kc2][yp]
        int kc2 = gid >> 4, yp = gid & 15;
        int k0 = 2 * kc2, y0 = 2 * yp;
        float4 v;
        v.x = c256[(k0 * y0) & 255];
        v.y = c256[(k0 * (y0 + 1)) & 255];
        v.z = c256[((k0 + 1) * y0) & 255];
        v.w = c256[((k0 + 1) * (y0 + 1)) & 255];
        g_B2[gid] = v;
    }
}

// ---------------------------------------------------------------------------
// F: fused DHT + channel mix + folded inverse transforms + zero-fill.
// One block per (b, blk, x); 256 threads.
//   A    : 4i x 2y register tile, k split across 2 warp-groups (partials)
//   mix  : thread (yg,o); sums the two A partials while reading
//   out  : warp -> (o-oct, k-half); lane -> k-quad. rst reads are
//          warp-uniform float4 broadcasts; M reads fully coalesced LDG.128
// ---------------------------------------------------------------------------
__global__ __launch_bounds__(256) void f_fused(const float* __restrict__ xin,
                                               const float* __restrict__ w1,
                                               const float* __restrict__ w2,
                                               float* __restrict__ out) {
    __shared__ float4 xs4[32 * 64];     // [i][kc] natural layout, 32 KB
    __shared__ float  As_p[2][32 * 36]; // k-half partials of A, pitch 36
    __shared__ float  rst[32 * 36];     // [y][o], pitch 36 (float4-readable)

    int t    = threadIdx.x;
    int lane = t & 31, warp = t >> 5;
    int bid  = blockIdx.x;
    int x    = bid & 31;
    int blk  = (bid >> 5) & 1;
    int b    = bid >> 6;
    int row  = blk ? (224 + x) : x;
    const float* w = blk ? w2 : w1;

    // ---- zero-fill dead rows [32,224): each block does half of one image ----
    {
        int img = bid >> 1, half = bid & 1;
        float4* o4 = (float4*)out + (size_t)img * 16384 + 2048 + half * 6144 + t;
#pragma unroll
        for (int j = 0; j < 24; j++) o4[j * 256] = make_float4(0.f, 0.f, 0.f, 0.f);
    }

    // ---- load x rows (natural layout, coalesced, conflict-free) ----
    const float4* xb4 = (const float4*)(xin + (((size_t)b * 32) * S + row) * S);
#pragma unroll
    for (int n = t; n < 2048; n += 256) {
        int i = n >> 6, kc = n & 63;
        xs4[n] = xb4[(size_t)i * (S * S / 4) + kc];
    }
    __syncthreads();

    // ---- phase A: corner DHT, 4i x 2y tile, k-half per warp-group ----
    {
        int kh = warp >> 2;                       // 0 or 1 (k-half)
        int iq = ((warp & 3) << 1) | (lane >> 4); // 0..7 (i-quad)
        int yp = lane & 15;                       // 0..15 (y-pair)
        float2 acc[4];
#pragma unroll
        for (int r = 0; r < 4; r++) acc[r] = make_float2(0.f, 0.f);
        const float4* xr = xs4 + iq * 4 * 64;
        const float4* Bp = g_B2 + yp;
#pragma unroll 8
        for (int j = 0; j < 32; j++) {
            int kc = kh * 32 + j;
            float4 b01 = __ldg(&Bp[(2 * kc) * 16]);      // k=4kc,4kc+1 x y-pair
            float4 b23 = __ldg(&Bp[(2 * kc + 1) * 16]);  // k=4kc+2,4kc+3
            float4 xv[4];
            xv[0] = xr[kc]; xv[1] = xr[kc + 64];
            xv[2] = xr[kc + 128]; xv[3] = xr[kc + 192];
#pragma unroll
            for (int r = 0; r < 4; r++) {
                acc[r].x += xv[r].x * b01.x + xv[r].y * b01.z
                          + xv[r].z * b23.x + xv[r].w * b23.z;
                acc[r].y += xv[r].x * b01.y + xv[r].y * b01.w
                          + xv[r].z * b23.y + xv[r].w * b23.w;
            }
        }
#pragma unroll
        for (int r = 0; r < 4; r++) {
            As_p[kh][(4 * iq + r) * 36 + 2 * yp]     = acc[r].x;
            As_p[kh][(4 * iq + r) * 36 + 2 * yp + 1] = acc[r].y;
        }
    }
    __syncthreads();

    // ---- phase 1: channel mix; sums both k-half partials of A ----
    {
        int yg = t & 7, o = t >> 3;
        float4 acc = make_float4(0.f, 0.f, 0.f, 0.f);
        const float4* wp  = (const float4*)(w + (size_t)o * 1024 + x * 32 + 4 * yg);
        const float4* ap0 = (const float4*)(As_p[0] + 4 * yg);
        const float4* ap1 = (const float4*)(As_p[1] + 4 * yg);
#pragma unroll 8
        for (int i = 0; i < 32; i++) {
            float4 wv = __ldg(&wp[(size_t)i * 8192]);
            float4 a0 = ap0[i * 9];
            float4 a1 = ap1[i * 9];
            acc.x += (a0.x + a1.x) * wv.x;
            acc.y += (a0.y + a1.y) * wv.y;
            acc.z += (a0.z + a1.z) * wv.z;
            acc.w += (a0.w + a1.w) * wv.w;
        }
        rst[(4 * yg + 0) * 36 + o] = acc.x;
        rst[(4 * yg + 1) * 36 + o] = acc.y;
        rst[(4 * yg + 2) * 36 + o] = acc.z;
        rst[(4 * yg + 3) * 36 + o] = acc.w;
    }
    __syncthreads();

    // ---- phase 2: trailing transforms. warp -> (o-oct, k-half); lane -> k4 ----
    {
        int ob    = 8 * (warp & 3);              // o-oct base
        int kbase = (warp >> 2) * 128 + 4 * lane;
        float4 acc[8];
#pragma unroll
        for (int j = 0; j < 8; j++) acc[j] = make_float4(0.f, 0.f, 0.f, 0.f);
        const float4* Mp = (const float4*)(g_M + kbase);
#pragma unroll 8
        for (int yy = 0; yy < 32; yy++) {
            float4 ra = *(const float4*)&rst[yy * 36 + ob];      // warp-uniform
            float4 rb = *(const float4*)&rst[yy * 36 + ob + 4];  // warp-uniform
            float4 mv = __ldg(&Mp[yy * 64]);                     // coalesced
            acc[0].x += ra.x * mv.x; acc[0].y += ra.x * mv.y;
            acc[0].z += ra.x * mv.z; acc[0].w += ra.x * mv.w;
            acc[1].x += ra.y * mv.x; acc[1].y += ra.y * mv.y;
            acc[1].z += ra.y * mv.z; acc[1].w += ra.y * mv.w;
            acc[2].x += ra.z * mv.x; acc[2].y += ra.z * mv.y;
            acc[2].z += ra.z * mv.z; acc[2].w += ra.z * mv.w;
            acc[3].x += ra.w * mv.x; acc[3].y += ra.w * mv.y;
            acc[3].z += ra.w * mv.z; acc[3].w += ra.w * mv.w;
            acc[4].x += rb.x * mv.x; acc[4].y += rb.x * mv.y;
            acc[4].z += rb.x * mv.z; acc[4].w += rb.x * mv.w;
            acc[5].x += rb.y * mv.x; acc[5].y += rb.y * mv.y;
            acc[5].z += rb.y * mv.z; acc[5].w += rb.y * mv.w;
            acc[6].x += rb.z * mv.x; acc[6].y += rb.z * mv.y;
            acc[6].z += rb.z * mv.z; acc[6].w += rb.z * mv.w;
            acc[7].x += rb.w * mv.x; acc[7].y += rb.w * mv.y;
            acc[7].z += rb.w * mv.z; acc[7].w += rb.w * mv.w;
        }
        float* op = out + (((size_t)(b * 32 + ob)) * S + row) * S + kbase;
#pragma unroll
        for (int j = 0; j < 8; j++)
            *(float4*)(op + (size_t)j * (S * S)) = acc[j];
    }
}

// ---------------------------------------------------------------------------
extern "C" void kernel_launch(void* const* d_in, const int* in_sizes, int n_in,
                              void* d_out, int out_size) {
    const float* x  = (const float*)d_in[0];
    const float* w1 = (const float*)d_in[1];
    const float* w2 = (const float*)d_in[2];
    float* out = (float*)d_out;

    k0_tables<<<32, 256>>>();
    f_fused<<<NB * 2 * 32, 256>>>(x, w1, w2, out);
}

// round 8
// speedup vs baseline: 1.0360x; 1.0360x over previous
#include <cuda_runtime.h>

// SpectralConv2d via DHT — fused kernel (R6 structure), single-wave residency:
// __launch_bounds__(256,4) caps regs at 64 so all 512 blocks fit in one wave.
//
//   A[i][y]   = sum_k x[b,i,row,k] * B[k][y],   B[k][y]=cas(2pi*k*y/256), y<32
//   r[o][y]   = sum_i A[i][y] * w_blk[i,o,x,y]
//   out[o][k] = sum_y r[o][y] * M[y][k]   for the 64 live rows; 0 elsewhere
//   M[y][k]   = ( sum_j cas(2pi*y*j/32) * cas(2pi*j*k/256) ) * 2^-42

#define NB 8
#define S  256

__device__ float4 g_Bt[64 * 32];   // [kc][y] = {B[4kc][y]..B[4kc+3][y]}
__device__ float  g_M[32 * 256];   // folded trailing transforms

// ---------------------------------------------------------------------------
// K0: build g_Bt and the folded 32x256 matrix M.
// ---------------------------------------------------------------------------
__global__ void k0_tables() {
    __shared__ float c256[256];
    __shared__ float c32[32];
    const float TWO_PI = 6.283185307179586476925286766559f;
    int t = threadIdx.x;
    {
        float s, c;
        sincosf((TWO_PI / 256.0f) * (float)t, &s, &c);
        c256[t] = c + s;
        if (t < 32) {
            float s2, c2;
            sincosf((TWO_PI / 32.0f) * (float)t, &s2, &c2);
            c32[t] = c2 + s2;
        }
    }
    __syncthreads();
    int gid = blockIdx.x * 256 + t;          // 0..8191
    {   // M[y][k]
        int y = gid >> 8, k = gid & 255;
        float acc = 0.0f;
#pragma unroll
        for (int j = 0; j < 32; j++)
            acc += c32[(y * j) & 31] * c256[(j * k) & 255];
        g_M[gid] = acc * 0x1p-42f;
    }
    if (gid < 2048) {                        // g_Bt[kc][y]
        int kc = gid >> 5, y = gid & 31;
        float4 v;
        v.x = c256[((4 * kc + 0) * y) & 255];
        v.y = c256[((4 * kc + 1) * y) & 255];
        v.z = c256[((4 * kc + 2) * y) & 255];
        v.w = c256[((4 * kc + 3) * y) & 255];
        g_Bt[gid] = v;
    }
}

// ---------------------------------------------------------------------------
// F: fused DHT + channel mix + folded inverse transforms + zero-fill.
// One block per (b, blk, x); 256 threads; 4 blocks/SM (single wave, grid 512).
// ---------------------------------------------------------------------------
__global__ __launch_bounds__(256, 4) void f_fused(const float* __restrict__ xin,
                                                  const float* __restrict__ w1,
                                                  const float* __restrict__ w2,
                                                  float* __restrict__ out) {
    __shared__ float4 xs4[32 * 64];   // [i][kc]  natural layout, 32 KB
    __shared__ float  As[32 * 36];    // [i][y]   pitch 36 (float4-aligned)
    __shared__ float  rst[32 * 33];   // [y][o]   pitch 33 (conflict-free writes)

    int t   = threadIdx.x;
    int bid = blockIdx.x;
    int x   = bid & 31;
    int blk = (bid >> 5) & 1;
    int b   = bid >> 6;
    int row = blk ? (224 + x) : x;
    const float* w = blk ? w2 : w1;

    // ---- zero-fill dead rows [32,224): each block does half of one image ----
    {
        int img = bid >> 1, half = bid & 1;
        float4* o4 = (float4*)out + (size_t)img * 16384 + 2048 + half * 6144 + t;
#pragma unroll
        for (int j = 0; j < 24; j++) o4[j * 256] = make_float4(0.f, 0.f, 0.f, 0.f);
    }

    // ---- load x rows (natural layout, coalesced, conflict-free) ----
    const float4* xb4 = (const float4*)(xin + (((size_t)b * 32) * S + row) * S);
#pragma unroll
    for (int n = t; n < 2048; n += 256) {
        int i = n >> 6, kc = n & 63;
        xs4[n] = xb4[(size_t)i * (S * S / 4) + kc];
    }
    __syncthreads();

    // ---- phase A: corner DHT. thread (y=lane, ig=warp) -> A[4ig..4ig+3][y] ----
    {
        int y = t & 31, ig = t >> 5;
        float a0 = 0.f, a1 = 0.f, a2 = 0.f, a3 = 0.f;
        const float4* Bt = g_Bt + y;
        const float4* xr = xs4 + 4 * ig * 64;
#pragma unroll 8
        for (int kc = 0; kc < 64; kc++) {
            float4 bv = __ldg(&Bt[kc * 32]);         // coalesced across lanes
            float4 x0 = xr[kc];                      // i = 4ig   (broadcast)
            float4 x1 = xr[kc + 64];                 // i = 4ig+1
            float4 x2 = xr[kc + 128];
            float4 x3 = xr[kc + 192];
            a0 += x0.x*bv.x + x0.y*bv.y + x0.z*bv.z + x0.w*bv.w;
            a1 += x1.x*bv.x + x1.y*bv.y + x1.z*bv.z + x1.w*bv.w;
            a2 += x2.x*bv.x + x2.y*bv.y + x2.z*bv.z + x2.w*bv.w;
            a3 += x3.x*bv.x + x3.y*bv.y + x3.z*bv.z + x3.w*bv.w;
        }
        As[(4 * ig + 0) * 36 + y] = a0;
        As[(4 * ig + 1) * 36 + y] = a1;
        As[(4 * ig + 2) * 36 + y] = a2;
        As[(4 * ig + 3) * 36 + y] = a3;
    }
    __syncthreads();

    // ---- phase 1: channel mix. thread (yg = t&7, o = t>>3) ----
    {
        int yg = t & 7, o = t >> 3;
        float4 acc = make_float4(0.f, 0.f, 0.f, 0.f);
        const float4* wp = (const float4*)(w + (size_t)o * 1024 + x * 32 + 4 * yg);
        const float4* ap = (const float4*)(As + 4 * yg);
#pragma unroll 8
        for (int i = 0; i < 32; i++) {
            float4 wv = __ldg(&wp[(size_t)i * 8192]);  // 32768 floats / 4
            float4 av = ap[i * 9];                     // 36 floats / 4
            acc.x += av.x * wv.x;
            acc.y += av.y * wv.y;
            acc.z += av.z * wv.z;
            acc.w += av.w * wv.w;
        }
        rst[(4 * yg + 0) * 33 + o] = acc.x;
        rst[(4 * yg + 1) * 33 + o] = acc.y;
        rst[(4 * yg + 2) * 33 + o] = acc.z;
        rst[(4 * yg + 3) * 33 + o] = acc.w;
    }
    __syncthreads();

    // ---- phase 2: trailing transforms; two 4-o passes (16 acc regs each) ----
    {
        int k4    = (t & 63) * 4;
        int obase = (t >> 6) * 8;                // uniform per warp pair
        const float4* Mp = (const float4*)(g_M + k4);
#pragma unroll
        for (int half = 0; half < 2; half++) {
            int ob = obase + 4 * half;
            float4 acc[4];
#pragma unroll
            for (int j = 0; j < 4; j++) acc[j] = make_float4(0.f, 0.f, 0.f, 0.f);
#pragma unroll 8
            for (int yy = 0; yy < 32; yy++) {
                float4 mv = __ldg(&Mp[yy * 64]);     // coalesced, L1-resident
                const float* rp = rst + yy * 33 + ob;
#pragma unroll
                for (int j = 0; j < 4; j++) {
                    float rv = rp[j];                // warp-uniform broadcast
                    acc[j].x += rv * mv.x;
                    acc[j].y += rv * mv.y;
                    acc[j].z += rv * mv.z;
                    acc[j].w += rv * mv.w;
                }
            }
            float* op = out + (((size_t)(b * 32 + ob)) * S + row) * S + k4;
#pragma unroll
            for (int j = 0; j < 4; j++)
                *(float4*)(op + (size_t)j * (S * S)) = acc[j];
        }
    }
}

// ---------------------------------------------------------------------------
extern "C" void kernel_launch(void* const* d_in, const int* in_sizes, int n_in,
                              void* d_out, int out_size) {
    const float* x  = (const float*)d_in[0];
    const float* w1 = (const float*)d_in[1];
    const float* w2 = (const float*)d_in[2];
    float* out = (float*)d_out;

    k0_tables<<<32, 256>>>();
    f_fused<<<NB * 2 * 32, 256>>>(x, w1, w2, out);
}